// round 2
// baseline (speedup 1.0000x reference)
#include <cuda_runtime.h>
#include <cuda_bf16.h>
#include <math.h>

// Problem constants
#define TT 4096   // tokens = B*S
#define DD 2048   // model dim
#define EE 8      // experts
#define FF 4096   // ffn dim
// top_k = 2 (read from input but assumed 2)

// Scratch (device globals: allocation-free per harness rules)
__device__ int   g_cnt[EE];
__device__ int   g_list[EE * TT];          // assignment ids (t*2+k), grouped per expert
__device__ float g_wts[2 * TT];            // combine weight per assignment id
__device__ float g_h[(size_t)2 * TT * FF]; // 134 MB: H per assignment
__device__ float g_o[(size_t)2 * TT * DD]; // 67 MB: weighted per-assignment output

// ---------------------------------------------------------------------------
__global__ void zero_kernel() {
    if (threadIdx.x < EE) g_cnt[threadIdx.x] = 0;
}

// ---------------------------------------------------------------------------
// Router: one warp per token. logits = x @ Wg^T, top-2, normalized weights.
__global__ __launch_bounds__(256) void router_kernel(
    const float* __restrict__ x, const float* __restrict__ Wg,
    float* __restrict__ logits_out)
{
    int warp = (blockIdx.x * blockDim.x + threadIdx.x) >> 5;
    int lane = threadIdx.x & 31;
    if (warp >= TT) return;
    const float* xr = x + (size_t)warp * DD;

    float acc[EE];
#pragma unroll
    for (int e = 0; e < EE; e++) acc[e] = 0.f;

    for (int d = lane; d < DD; d += 32) {
        float xv = xr[d];
#pragma unroll
        for (int e = 0; e < EE; e++) acc[e] += xv * Wg[e * DD + d];
    }
#pragma unroll
    for (int e = 0; e < EE; e++) {
#pragma unroll
        for (int off = 16; off; off >>= 1)
            acc[e] += __shfl_xor_sync(0xffffffffu, acc[e], off);
    }
    if (lane == 0) {
#pragma unroll
        for (int e = 0; e < EE; e++) logits_out[warp * EE + e] = acc[e];
        // top-2 (first occurrence on ties, matching lax.top_k)
        int i0 = 0;
#pragma unroll
        for (int e = 1; e < EE; e++) if (acc[e] > acc[i0]) i0 = e;
        int i1 = -1;
#pragma unroll
        for (int e = 0; e < EE; e++) {
            if (e == i0) continue;
            if (i1 < 0 || acc[e] > acc[i1]) i1 = e;
        }
        float m  = fmaxf(acc[i0], acc[i1]);
        float e0 = expf(acc[i0] - m);
        float e1 = expf(acc[i1] - m);
        float inv = 1.f / (e0 + e1);
        g_wts[2 * warp + 0] = e0 * inv;
        g_wts[2 * warp + 1] = e1 * inv;
        int p0 = atomicAdd(&g_cnt[i0], 1);
        g_list[i0 * TT + p0] = 2 * warp + 0;
        int p1 = atomicAdd(&g_cnt[i1], 1);
        g_list[i1 * TT + p1] = 2 * warp + 1;
    }
}

// ---------------------------------------------------------------------------
// Pass A: per-expert H = silu(Xg@W1) * (Xg@W3). 64x64 tile, BK=16, 256 thr.
#define BM 64
#define BN 64
#define BK 16

__global__ __launch_bounds__(256) void ffn_up_kernel(
    const float* __restrict__ x,
    const float* __restrict__ W1,
    const float* __restrict__ W3)
{
    int e  = blockIdx.z;
    int rt = blockIdx.y;           // row tile within expert list
    int ct = blockIdx.x;           // col tile within F
    int cnt = g_cnt[e];
    if (rt * BM >= cnt) return;

    __shared__ float As[BK][BM];
    __shared__ float B1s[BK][BN];
    __shared__ float B3s[BK][BN];
    __shared__ int   aid[BM];

    int tid = threadIdx.x;
    if (tid < BM) {
        int r = rt * BM + tid;
        aid[tid] = (r < cnt) ? g_list[e * TT + r] : -1;
    }
    __syncthreads();

    float acc1[4][4] = {};
    float acc3[4][4] = {};
    int ty = tid >> 4, tx = tid & 15;

    const float* W1p = W1 + (size_t)e * DD * FF + (size_t)ct * BN;
    const float* W3p = W3 + (size_t)e * DD * FF + (size_t)ct * BN;

    int ar = tid >> 2;             // A-load row (0..63)
    int akb = (tid & 3) * 4;       // A-load k base (0,4,8,12)
    int a_of_row = aid[ar];
    const float* xrow = (a_of_row >= 0) ? (x + (size_t)(a_of_row >> 1) * DD) : x;

    int bkk = tid >> 4;            // B-load row (0..15)
    int bcb = (tid & 15) * 4;      // B-load col base

    for (int k0 = 0; k0 < DD; k0 += BK) {
        __syncthreads();
        float4 va = make_float4(0.f, 0.f, 0.f, 0.f);
        if (a_of_row >= 0) va = *(const float4*)&xrow[k0 + akb];
        As[akb + 0][ar] = va.x;
        As[akb + 1][ar] = va.y;
        As[akb + 2][ar] = va.z;
        As[akb + 3][ar] = va.w;

        float4 v1 = *(const float4*)&W1p[(size_t)(k0 + bkk) * FF + bcb];
        float4 v3 = *(const float4*)&W3p[(size_t)(k0 + bkk) * FF + bcb];
        *(float4*)&B1s[bkk][bcb] = v1;
        *(float4*)&B3s[bkk][bcb] = v3;
        __syncthreads();

#pragma unroll
        for (int kk = 0; kk < BK; kk++) {
            float4 av = *(const float4*)&As[kk][ty * 4];
            float4 b1 = *(const float4*)&B1s[kk][tx * 4];
            float4 b3 = *(const float4*)&B3s[kk][tx * 4];
            float a4[4] = {av.x, av.y, av.z, av.w};
            float c1[4] = {b1.x, b1.y, b1.z, b1.w};
            float c3[4] = {b3.x, b3.y, b3.z, b3.w};
#pragma unroll
            for (int i = 0; i < 4; i++) {
#pragma unroll
                for (int j = 0; j < 4; j++) {
                    acc1[i][j] = fmaf(a4[i], c1[j], acc1[i][j]);
                    acc3[i][j] = fmaf(a4[i], c3[j], acc3[i][j]);
                }
            }
        }
    }

#pragma unroll
    for (int i = 0; i < 4; i++) {
        int r = ty * 4 + i;
        int a = aid[r];
        if (a < 0) continue;
        float* hp = g_h + (size_t)a * FF + (size_t)ct * BN + tx * 4;
        float4 o;
        float v;
        v = acc1[i][0]; o.x = (v / (1.f + expf(-v))) * acc3[i][0];
        v = acc1[i][1]; o.y = (v / (1.f + expf(-v))) * acc3[i][1];
        v = acc1[i][2]; o.z = (v / (1.f + expf(-v))) * acc3[i][2];
        v = acc1[i][3]; o.w = (v / (1.f + expf(-v))) * acc3[i][3];
        *(float4*)hp = o;
    }
}

// ---------------------------------------------------------------------------
// Pass B: O[a] = w_a * (H[a] @ W2_e). 64x64 tile over [rows, D], K over F.
__global__ __launch_bounds__(256) void ffn_down_kernel(
    const float* __restrict__ W2)
{
    int e  = blockIdx.z;
    int rt = blockIdx.y;
    int ct = blockIdx.x;           // col tile within D
    int cnt = g_cnt[e];
    if (rt * BM >= cnt) return;

    __shared__ float As[BK][BM];
    __shared__ float Bs[BK][BN];
    __shared__ int   aid[BM];

    int tid = threadIdx.x;
    if (tid < BM) {
        int r = rt * BM + tid;
        aid[tid] = (r < cnt) ? g_list[e * TT + r] : -1;
    }
    __syncthreads();

    float acc[4][4] = {};
    int ty = tid >> 4, tx = tid & 15;

    const float* W2p = W2 + (size_t)e * FF * DD + (size_t)ct * BN;

    int ar = tid >> 2;
    int akb = (tid & 3) * 4;
    int a_of_row = aid[ar];
    const float* hrow = (a_of_row >= 0) ? (g_h + (size_t)a_of_row * FF) : g_h;

    int bkk = tid >> 4;
    int bcb = (tid & 15) * 4;

    for (int k0 = 0; k0 < FF; k0 += BK) {
        __syncthreads();
        float4 va = make_float4(0.f, 0.f, 0.f, 0.f);
        if (a_of_row >= 0) va = *(const float4*)&hrow[k0 + akb];
        As[akb + 0][ar] = va.x;
        As[akb + 1][ar] = va.y;
        As[akb + 2][ar] = va.z;
        As[akb + 3][ar] = va.w;

        float4 vb = *(const float4*)&W2p[(size_t)(k0 + bkk) * DD + bcb];
        *(float4*)&Bs[bkk][bcb] = vb;
        __syncthreads();

#pragma unroll
        for (int kk = 0; kk < BK; kk++) {
            float4 av = *(const float4*)&As[kk][ty * 4];
            float4 bv = *(const float4*)&Bs[kk][tx * 4];
            float a4[4] = {av.x, av.y, av.z, av.w};
            float c4[4] = {bv.x, bv.y, bv.z, bv.w};
#pragma unroll
            for (int i = 0; i < 4; i++) {
#pragma unroll
                for (int j = 0; j < 4; j++)
                    acc[i][j] = fmaf(a4[i], c4[j], acc[i][j]);
            }
        }
    }

#pragma unroll
    for (int i = 0; i < 4; i++) {
        int r = ty * 4 + i;
        int a = aid[r];
        if (a < 0) continue;
        float w = g_wts[a];
        float* op = g_o + (size_t)a * DD + (size_t)ct * BN + tx * 4;
        float4 o;
        o.x = w * acc[i][0];
        o.y = w * acc[i][1];
        o.z = w * acc[i][2];
        o.w = w * acc[i][3];
        *(float4*)op = o;
    }
}

// ---------------------------------------------------------------------------
// Combine: y[t] = O[2t] + O[2t+1]
__global__ __launch_bounds__(256) void combine_kernel(float* __restrict__ y)
{
    size_t i = ((size_t)blockIdx.x * blockDim.x + threadIdx.x) * 4;
    if (i >= (size_t)TT * DD) return;
    int t = (int)(i / DD);
    int d = (int)(i % DD);
    float4 a = *(const float4*)&g_o[((size_t)2 * t) * DD + d];
    float4 b = *(const float4*)&g_o[((size_t)2 * t + 1) * DD + d];
    float4 o;
    o.x = a.x + b.x; o.y = a.y + b.y; o.z = a.z + b.z; o.w = a.w + b.w;
    *(float4*)&y[i] = o;
}

// ---------------------------------------------------------------------------
extern "C" void kernel_launch(void* const* d_in, const int* in_sizes, int n_in,
                              void* d_out, int out_size)
{
    const float* x  = (const float*)d_in[0];
    const float* Wg = (const float*)d_in[1];
    const float* W1 = (const float*)d_in[2];
    const float* W3 = (const float*)d_in[3];
    const float* W2 = (const float*)d_in[4];
    // d_in[5] = top_k (assumed 2)

    float* y      = (float*)d_out;                 // [T, D]
    float* logits = y + (size_t)TT * DD;           // [T, E]

    zero_kernel<<<1, 32>>>();
    router_kernel<<<(TT * 32 + 255) / 256, 256>>>(x, Wg, logits);
    {
        dim3 grid(FF / BN, TT / BM, EE);
        ffn_up_kernel<<<grid, 256>>>(x, W1, W3);
    }
    {
        dim3 grid(DD / BN, TT / BM, EE);
        ffn_down_kernel<<<grid, 256>>>(W2);
    }
    combine_kernel<<<(TT * DD / 4 + 255) / 256, 256>>>(y);
}

// round 7
// speedup vs baseline: 3.4161x; 3.4161x over previous
#include <cuda_runtime.h>
#include <cuda_fp16.h>
#include <math.h>
#include <stdint.h>

#define TT 4096   // tokens
#define DD 2048   // model dim
#define EE 8      // experts
#define FF 4096   // ffn dim
#define NA (2*TT) // assignments (top_k = 2)

// ---------------------------------------------------------------------------
// Helpers
// ---------------------------------------------------------------------------
__device__ __forceinline__ uint32_t smem_u32(const void* p) {
    uint32_t a;
    asm("{ .reg .u64 t; cvta.to.shared.u64 t, %1; cvt.u32.u64 %0, t; }"
        : "=r"(a) : "l"(p));
    return a;
}
__device__ __forceinline__ uint32_t lds32(uint32_t addr) {
    uint32_t v;
    asm volatile("ld.shared.b32 %0, [%1];" : "=r"(v) : "r"(addr));
    return v;
}
__device__ __forceinline__ void mma16816(float* c, const uint32_t* a, const uint32_t* b) {
    asm volatile("mma.sync.aligned.m16n8k16.row.col.f32.f16.f16.f32 "
        "{%0,%1,%2,%3}, {%4,%5,%6,%7}, {%8,%9}, {%0,%1,%2,%3};"
        : "+f"(c[0]), "+f"(c[1]), "+f"(c[2]), "+f"(c[3])
        : "r"(a[0]), "r"(a[1]), "r"(a[2]), "r"(a[3]), "r"(b[0]), "r"(b[1]));
}
__device__ __forceinline__ uint32_t pk2(float a, float b) {
    __half2 h = __floats2half2_rn(a, b);
    return *(uint32_t*)&h;
}

// ---------------------------------------------------------------------------
// Device-global scratch (allocation-free)
// ---------------------------------------------------------------------------
__device__ int    g_mma_ok;
__device__ int    g_cnt[EE];
__device__ int    g_list[EE * TT];
__device__ float  g_wts[NA];

__device__ __half g_h16[(size_t)NA * FF];   // MMA path intermediate (fp16)
__device__ float  g_hf[(size_t)NA * FF];    // SIMT path intermediate (fp32)
__device__ float  g_o[(size_t)NA * DD];     // SIMT path per-assignment output

// ---------------------------------------------------------------------------
__global__ void zero_cnt_kernel() {
    if (threadIdx.x < EE) g_cnt[threadIdx.x] = 0;
}

__global__ __launch_bounds__(256) void zero_y_kernel(float* __restrict__ y) {
    size_t i = ((size_t)blockIdx.x * 256 + threadIdx.x) * 4;
    if (i < (size_t)TT * DD) *(float4*)&y[i] = make_float4(0.f, 0.f, 0.f, 0.f);
}

// Probe: does mma.sync.m16n8k16 produce correct results on this arch/toolchain?
__global__ void probe_kernel() {
    uint32_t one2 = 0x3C003C00u;                 // two fp16 1.0
    uint32_t a[4] = {one2, one2, one2, one2};
    uint32_t b[2] = {one2, one2};
    float c[4] = {0.f, 0.f, 0.f, 0.f};
    mma16816(c, a, b);
    if (threadIdx.x == 0)
        g_mma_ok = (fabsf(c[0] - 16.0f) < 0.5f &&
                    fabsf(c[3] - 16.0f) < 0.5f) ? 1 : 0;
}

// ---------------------------------------------------------------------------
// Router: one warp per token  (verified in R1)
__global__ __launch_bounds__(256) void router_kernel(
    const float* __restrict__ x, const float* __restrict__ Wg,
    float* __restrict__ logits_out)
{
    int warp = (blockIdx.x * blockDim.x + threadIdx.x) >> 5;
    int lane = threadIdx.x & 31;
    if (warp >= TT) return;
    const float* xr = x + (size_t)warp * DD;
    float acc[EE];
#pragma unroll
    for (int e = 0; e < EE; e++) acc[e] = 0.f;
    for (int d = lane; d < DD; d += 32) {
        float xv = xr[d];
#pragma unroll
        for (int e = 0; e < EE; e++) acc[e] += xv * Wg[e * DD + d];
    }
#pragma unroll
    for (int e = 0; e < EE; e++)
#pragma unroll
        for (int off = 16; off; off >>= 1)
            acc[e] += __shfl_xor_sync(0xffffffffu, acc[e], off);
    if (lane == 0) {
#pragma unroll
        for (int e = 0; e < EE; e++) logits_out[warp * EE + e] = acc[e];
        int i0 = 0;
#pragma unroll
        for (int e = 1; e < EE; e++) if (acc[e] > acc[i0]) i0 = e;
        int i1 = -1;
#pragma unroll
        for (int e = 0; e < EE; e++) {
            if (e == i0) continue;
            if (i1 < 0 || acc[e] > acc[i1]) i1 = e;
        }
        float m  = fmaxf(acc[i0], acc[i1]);
        float e0 = expf(acc[i0] - m);
        float e1 = expf(acc[i1] - m);
        float inv = 1.f / (e0 + e1);
        g_wts[2 * warp + 0] = e0 * inv;
        g_wts[2 * warp + 1] = e1 * inv;
        int p0 = atomicAdd(&g_cnt[i0], 1);
        g_list[i0 * TT + p0] = 2 * warp + 0;
        int p1 = atomicAdd(&g_cnt[i1], 1);
        g_list[i1 * TT + p1] = 2 * warp + 1;
    }
}

// ---------------------------------------------------------------------------
// Fragment loaders for pad-40 rows (80B row stride), k-contiguous tiles.
// m16n8k16 A row-major: a0=(r,k),(r,k+1); a1=(r+8,...); a2=(r,k+8..); a3=(r+8,k+8..)
__device__ __forceinline__ void ldfragA(uint32_t* a, uint32_t base, int R0, int ks, int lane) {
    int qr = lane >> 2;
    uint32_t kb = (uint32_t)(ks * 16 + (lane & 3) * 2) * 2u;
    uint32_t r0 = (uint32_t)(R0 + qr) * 80u;
    a[0] = lds32(base + r0 + kb);
    a[1] = lds32(base + r0 + 640u + kb);        // +8 rows
    a[2] = lds32(base + r0 + kb + 16u);         // +8 k
    a[3] = lds32(base + r0 + 640u + kb + 16u);
}
// B stored [n][k] (k-contig): b0=(k,n),(k+1,n); b1=(k+8,n),(k+9,n); n = N0+lane/4
__device__ __forceinline__ void ldfragB(uint32_t* b, uint32_t base, int N0, int ks, int lane) {
    int qn = lane >> 2;
    uint32_t kb = (uint32_t)(ks * 16 + (lane & 3) * 2) * 2u;
    uint32_t n0 = (uint32_t)(N0 + qn) * 80u;
    b[0] = lds32(base + n0 + kb);
    b[1] = lds32(base + n0 + kb + 16u);
}

// ---------------------------------------------------------------------------
// MMA Pass A (up): H = silu(Xg@W1) * (Xg@W3).  CTA 128 rows x 64 F-cols, BK=32.
// Plain LDG -> convert fp16 -> STS. B transposed via k-strided coalesced loads.
__global__ __launch_bounds__(256) void up_mma_kernel(
    const float* __restrict__ x, const float* __restrict__ W1,
    const float* __restrict__ W3)
{
    if (!g_mma_ok) return;
    int ct = blockIdx.x, rt = blockIdx.y, e = blockIdx.z;
    int cnt = g_cnt[e];
    if (rt * 128 >= cnt) return;

    __shared__ int aid[128];
    __shared__ __align__(16) __half As[128][40];
    __shared__ __align__(16) __half B1s[64][40];
    __shared__ __align__(16) __half B3s[64][40];

    int tid = threadIdx.x, wid = tid >> 5, lane = tid & 31;
    if (tid < 128) {
        int r = rt * 128 + tid;
        aid[tid] = (r < cnt) ? g_list[e * TT + r] : -1;
    }
    __syncthreads();

    // A: 2 threads/row, 16 fp32 each along k
    int arow = tid >> 1, akq = (tid & 1) * 16;
    int aa = aid[arow];
    const float* xrow = x + (size_t)((aa >= 0) ? (aa >> 1) : 0) * DD;
    // B: n = tid&63, k-group = (tid>>6)*8 ; reads W[k][n] (n coalesced per k)
    int bn = tid & 63, bkq = (tid >> 6) * 8;
    const float* w1p = W1 + (size_t)e * DD * FF + (size_t)ct * 64 + bn;
    const float* w3p = W3 + (size_t)e * DD * FF + (size_t)ct * 64 + bn;

    uint32_t aBase  = smem_u32(&As[0][0]);
    uint32_t b1Base = smem_u32(&B1s[0][0]);
    uint32_t b3Base = smem_u32(&B3s[0][0]);

    float acc1[2][4][4] = {}, acc3[2][4][4] = {};
    int wm = wid >> 1, wn = wid & 1;
    const int nc = DD / 32;            // 64 chunks

    float aR[16], b1R[8], b3R[8];
    // preload chunk 0
    {
        const float* xp = xrow + akq;
        *(float4*)(aR + 0)  = *(const float4*)(xp + 0);
        *(float4*)(aR + 4)  = *(const float4*)(xp + 4);
        *(float4*)(aR + 8)  = *(const float4*)(xp + 8);
        *(float4*)(aR + 12) = *(const float4*)(xp + 12);
#pragma unroll
        for (int i = 0; i < 8; i++) {
            b1R[i] = w1p[(size_t)(bkq + i) * FF];
            b3R[i] = w3p[(size_t)(bkq + i) * FF];
        }
    }

    for (int c = 0; c < nc; c++) {
        __syncthreads();
        // STS (convert to fp16)
        {
            uint32_t ap[8];
#pragma unroll
            for (int j = 0; j < 8; j++) ap[j] = pk2(aR[2*j], aR[2*j+1]);
            *(uint4*)&As[arow][akq]     = make_uint4(ap[0], ap[1], ap[2], ap[3]);
            *(uint4*)&As[arow][akq + 8] = make_uint4(ap[4], ap[5], ap[6], ap[7]);
            uint32_t bp[4], cp[4];
#pragma unroll
            for (int j = 0; j < 4; j++) {
                bp[j] = pk2(b1R[2*j], b1R[2*j+1]);
                cp[j] = pk2(b3R[2*j], b3R[2*j+1]);
            }
            *(uint4*)&B1s[bn][bkq] = make_uint4(bp[0], bp[1], bp[2], bp[3]);
            *(uint4*)&B3s[bn][bkq] = make_uint4(cp[0], cp[1], cp[2], cp[3]);
        }
        __syncthreads();
        if (c + 1 < nc) {               // prefetch next chunk into regs
            int k0 = (c + 1) * 32;
            const float* xp = xrow + k0 + akq;
            *(float4*)(aR + 0)  = *(const float4*)(xp + 0);
            *(float4*)(aR + 4)  = *(const float4*)(xp + 4);
            *(float4*)(aR + 8)  = *(const float4*)(xp + 8);
            *(float4*)(aR + 12) = *(const float4*)(xp + 12);
#pragma unroll
            for (int i = 0; i < 8; i++) {
                b1R[i] = w1p[(size_t)(k0 + bkq + i) * FF];
                b3R[i] = w3p[(size_t)(k0 + bkq + i) * FF];
            }
        }
#pragma unroll
        for (int ks = 0; ks < 2; ks++) {
            uint32_t a[2][4];
#pragma unroll
            for (int mt = 0; mt < 2; mt++)
                ldfragA(a[mt], aBase, wm * 32 + mt * 16, ks, lane);
#pragma unroll
            for (int nt = 0; nt < 4; nt++) {
                uint32_t b1[2], b3[2];
                ldfragB(b1, b1Base, wn * 32 + nt * 8, ks, lane);
                ldfragB(b3, b3Base, wn * 32 + nt * 8, ks, lane);
#pragma unroll
                for (int mt = 0; mt < 2; mt++) {
                    mma16816(acc1[mt][nt], a[mt], b1);
                    mma16816(acc3[mt][nt], a[mt], b3);
                }
            }
        }
    }

    // epilogue: silu(acc1)*acc3 -> g_h16
#pragma unroll
    for (int mt = 0; mt < 2; mt++) {
#pragma unroll
        for (int h = 0; h < 2; h++) {
            int row = wm * 32 + mt * 16 + (lane >> 2) + h * 8;
            int a = aid[row];
            if (a < 0) continue;
            __half* hp = g_h16 + (size_t)a * FF + (size_t)ct * 64 + wn * 32 + 2 * (lane & 3);
#pragma unroll
            for (int nt = 0; nt < 4; nt++) {
                float v1a = acc1[mt][nt][h*2],   v1b = acc1[mt][nt][h*2+1];
                float v3a = acc3[mt][nt][h*2],   v3b = acc3[mt][nt][h*2+1];
                float ha = (v1a / (1.f + expf(-v1a))) * v3a;
                float hb = (v1b / (1.f + expf(-v1b))) * v3b;
                *(__half2*)(hp + nt * 8) = __floats2half2_rn(ha, hb);
            }
        }
    }
}

// ---------------------------------------------------------------------------
// MMA Pass B (down): y += w * (H @ W2).  CTA 128 rows x 64 D-cols, BK=32 over F.
__global__ __launch_bounds__(256) void down_mma_kernel(
    const float* __restrict__ W2, float* __restrict__ y)
{
    if (!g_mma_ok) return;
    int ct = blockIdx.x, rt = blockIdx.y, e = blockIdx.z;
    int cnt = g_cnt[e];
    if (rt * 128 >= cnt) return;

    __shared__ int aid[128];
    __shared__ __align__(16) __half As[128][40];
    __shared__ __align__(16) __half Bs[64][40];

    int tid = threadIdx.x, wid = tid >> 5, lane = tid & 31;
    if (tid < 128) {
        int r = rt * 128 + tid;
        aid[tid] = (r < cnt) ? g_list[e * TT + r] : -1;
    }
    __syncthreads();

    int arow = tid >> 1, akq = (tid & 1) * 16;       // 16 halves each
    int aa = aid[arow];
    const __half* hrow = g_h16 + (size_t)((aa >= 0) ? aa : 0) * FF;
    int bn = tid & 63, bkq = (tid >> 6) * 8;
    const float* w2p = W2 + (size_t)e * FF * DD + (size_t)ct * 64 + bn;

    uint32_t aBase = smem_u32(&As[0][0]);
    uint32_t bBase = smem_u32(&Bs[0][0]);

    float acc[2][4][4] = {};
    int wm = wid >> 1, wn = wid & 1;
    const int nc = FF / 32;            // 128 chunks

    uint4 aU[2]; float bR[8];
    {
        const __half* hp = hrow + akq;
        aU[0] = *(const uint4*)(hp);
        aU[1] = *(const uint4*)(hp + 8);
#pragma unroll
        for (int i = 0; i < 8; i++) bR[i] = w2p[(size_t)(bkq + i) * DD];
    }

    for (int c = 0; c < nc; c++) {
        __syncthreads();
        {
            *(uint4*)&As[arow][akq]     = aU[0];
            *(uint4*)&As[arow][akq + 8] = aU[1];
            uint32_t bp[4];
#pragma unroll
            for (int j = 0; j < 4; j++) bp[j] = pk2(bR[2*j], bR[2*j+1]);
            *(uint4*)&Bs[bn][bkq] = make_uint4(bp[0], bp[1], bp[2], bp[3]);
        }
        __syncthreads();
        if (c + 1 < nc) {
            int k0 = (c + 1) * 32;
            const __half* hp = hrow + k0 + akq;
            aU[0] = *(const uint4*)(hp);
            aU[1] = *(const uint4*)(hp + 8);
#pragma unroll
            for (int i = 0; i < 8; i++) bR[i] = w2p[(size_t)(k0 + bkq + i) * DD];
        }
#pragma unroll
        for (int ks = 0; ks < 2; ks++) {
            uint32_t a[2][4];
#pragma unroll
            for (int mt = 0; mt < 2; mt++)
                ldfragA(a[mt], aBase, wm * 32 + mt * 16, ks, lane);
#pragma unroll
            for (int nt = 0; nt < 4; nt++) {
                uint32_t b[2];
                ldfragB(b, bBase, wn * 32 + nt * 8, ks, lane);
#pragma unroll
                for (int mt = 0; mt < 2; mt++)
                    mma16816(acc[mt][nt], a[mt], b);
            }
        }
    }

    // epilogue: exactly 2 commutative adds per y element -> deterministic
#pragma unroll
    for (int mt = 0; mt < 2; mt++) {
#pragma unroll
        for (int h = 0; h < 2; h++) {
            int row = wm * 32 + mt * 16 + (lane >> 2) + h * 8;
            int a = aid[row];
            if (a < 0) continue;
            float w = g_wts[a];
            float* yp = y + (size_t)(a >> 1) * DD + (size_t)ct * 64 + wn * 32 + 2 * (lane & 3);
#pragma unroll
            for (int nt = 0; nt < 4; nt++) {
                atomicAdd(yp + nt * 8,     w * acc[mt][nt][h*2]);
                atomicAdd(yp + nt * 8 + 1, w * acc[mt][nt][h*2+1]);
            }
        }
    }
}

// ---------------------------------------------------------------------------
// SIMT fallback: R1 kernels verbatim (verified passing), gated on !g_mma_ok
// ---------------------------------------------------------------------------
#define SBM 64
#define SBN 64
#define SBK 16

__global__ __launch_bounds__(256) void up_simt_kernel(
    const float* __restrict__ x, const float* __restrict__ W1,
    const float* __restrict__ W3)
{
    if (g_mma_ok) return;
    int e  = blockIdx.z;
    int rt = blockIdx.y;
    int ct = blockIdx.x;
    int cnt = g_cnt[e];
    if (rt * SBM >= cnt) return;

    __shared__ float As[SBK][SBM];
    __shared__ float B1s[SBK][SBN];
    __shared__ float B3s[SBK][SBN];
    __shared__ int   aid[SBM];

    int tid = threadIdx.x;
    if (tid < SBM) {
        int r = rt * SBM + tid;
        aid[tid] = (r < cnt) ? g_list[e * TT + r] : -1;
    }
    __syncthreads();

    float acc1[4][4] = {};
    float acc3[4][4] = {};
    int ty = tid >> 4, tx = tid & 15;

    const float* W1p = W1 + (size_t)e * DD * FF + (size_t)ct * SBN;
    const float* W3p = W3 + (size_t)e * DD * FF + (size_t)ct * SBN;

    int ar = tid >> 2;
    int akb = (tid & 3) * 4;
    int a_of_row = aid[ar];
    const float* xrow = (a_of_row >= 0) ? (x + (size_t)(a_of_row >> 1) * DD) : x;

    int bkk = tid >> 4;
    int bcb = (tid & 15) * 4;

    for (int k0 = 0; k0 < DD; k0 += SBK) {
        __syncthreads();
        float4 va = make_float4(0.f, 0.f, 0.f, 0.f);
        if (a_of_row >= 0) va = *(const float4*)&xrow[k0 + akb];
        As[akb + 0][ar] = va.x;
        As[akb + 1][ar] = va.y;
        As[akb + 2][ar] = va.z;
        As[akb + 3][ar] = va.w;
        float4 v1 = *(const float4*)&W1p[(size_t)(k0 + bkk) * FF + bcb];
        float4 v3 = *(const float4*)&W3p[(size_t)(k0 + bkk) * FF + bcb];
        *(float4*)&B1s[bkk][bcb] = v1;
        *(float4*)&B3s[bkk][bcb] = v3;
        __syncthreads();
#pragma unroll
        for (int kk = 0; kk < SBK; kk++) {
            float4 av = *(const float4*)&As[kk][ty * 4];
            float4 b1 = *(const float4*)&B1s[kk][tx * 4];
            float4 b3 = *(const float4*)&B3s[kk][tx * 4];
            float a4[4] = {av.x, av.y, av.z, av.w};
            float c1[4] = {b1.x, b1.y, b1.z, b1.w};
            float c3[4] = {b3.x, b3.y, b3.z, b3.w};
#pragma unroll
            for (int i = 0; i < 4; i++)
#pragma unroll
                for (int j = 0; j < 4; j++) {
                    acc1[i][j] = fmaf(a4[i], c1[j], acc1[i][j]);
                    acc3[i][j] = fmaf(a4[i], c3[j], acc3[i][j]);
                }
        }
    }
#pragma unroll
    for (int i = 0; i < 4; i++) {
        int r = ty * 4 + i;
        int a = aid[r];
        if (a < 0) continue;
        float* hp = g_hf + (size_t)a * FF + (size_t)ct * SBN + tx * 4;
        float4 o; float v;
        v = acc1[i][0]; o.x = (v / (1.f + expf(-v))) * acc3[i][0];
        v = acc1[i][1]; o.y = (v / (1.f + expf(-v))) * acc3[i][1];
        v = acc1[i][2]; o.z = (v / (1.f + expf(-v))) * acc3[i][2];
        v = acc1[i][3]; o.w = (v / (1.f + expf(-v))) * acc3[i][3];
        *(float4*)hp = o;
    }
}

__global__ __launch_bounds__(256) void down_simt_kernel(const float* __restrict__ W2)
{
    if (g_mma_ok) return;
    int e  = blockIdx.z;
    int rt = blockIdx.y;
    int ct = blockIdx.x;
    int cnt = g_cnt[e];
    if (rt * SBM >= cnt) return;

    __shared__ float As[SBK][SBM];
    __shared__ float Bs[SBK][SBN];
    __shared__ int   aid[SBM];

    int tid = threadIdx.x;
    if (tid < SBM) {
        int r = rt * SBM + tid;
        aid[tid] = (r < cnt) ? g_list[e * TT + r] : -1;
    }
    __syncthreads();

    float acc[4][4] = {};
    int ty = tid >> 4, tx = tid & 15;
    const float* W2p = W2 + (size_t)e * FF * DD + (size_t)ct * SBN;

    int ar = tid >> 2;
    int akb = (tid & 3) * 4;
    int a_of_row = aid[ar];
    const float* hrow = (a_of_row >= 0) ? (g_hf + (size_t)a_of_row * FF) : g_hf;

    int bkk = tid >> 4;
    int bcb = (tid & 15) * 4;

    for (int k0 = 0; k0 < FF; k0 += SBK) {
        __syncthreads();
        float4 va = make_float4(0.f, 0.f, 0.f, 0.f);
        if (a_of_row >= 0) va = *(const float4*)&hrow[k0 + akb];
        As[akb + 0][ar] = va.x;
        As[akb + 1][ar] = va.y;
        As[akb + 2][ar] = va.z;
        As[akb + 3][ar] = va.w;
        float4 vb = *(const float4*)&W2p[(size_t)(k0 + bkk) * DD + bcb];
        *(float4*)&Bs[bkk][bcb] = vb;
        __syncthreads();
#pragma unroll
        for (int kk = 0; kk < SBK; kk++) {
            float4 av = *(const float4*)&As[kk][ty * 4];
            float4 bv = *(const float4*)&Bs[kk][tx * 4];
            float a4[4] = {av.x, av.y, av.z, av.w};
            float c4[4] = {bv.x, bv.y, bv.z, bv.w};
#pragma unroll
            for (int i = 0; i < 4; i++)
#pragma unroll
                for (int j = 0; j < 4; j++)
                    acc[i][j] = fmaf(a4[i], c4[j], acc[i][j]);
        }
    }
#pragma unroll
    for (int i = 0; i < 4; i++) {
        int r = ty * 4 + i;
        int a = aid[r];
        if (a < 0) continue;
        float w = g_wts[a];
        float* op = g_o + (size_t)a * DD + (size_t)ct * SBN + tx * 4;
        float4 o;
        o.x = w * acc[i][0]; o.y = w * acc[i][1];
        o.z = w * acc[i][2]; o.w = w * acc[i][3];
        *(float4*)op = o;
    }
}

__global__ __launch_bounds__(256) void combine_simt_kernel(float* __restrict__ y)
{
    if (g_mma_ok) return;
    size_t i = ((size_t)blockIdx.x * blockDim.x + threadIdx.x) * 4;
    if (i >= (size_t)TT * DD) return;
    int t = (int)(i / DD);
    int d = (int)(i % DD);
    float4 a = *(const float4*)&g_o[((size_t)2 * t) * DD + d];
    float4 b = *(const float4*)&g_o[((size_t)2 * t + 1) * DD + d];
    float4 o;
    o.x = a.x + b.x; o.y = a.y + b.y; o.z = a.z + b.z; o.w = a.w + b.w;
    *(float4*)&y[i] = o;
}

// ---------------------------------------------------------------------------
extern "C" void kernel_launch(void* const* d_in, const int* in_sizes, int n_in,
                              void* d_out, int out_size)
{
    const float* x  = (const float*)d_in[0];
    const float* Wg = (const float*)d_in[1];
    const float* W1 = (const float*)d_in[2];
    const float* W3 = (const float*)d_in[3];
    const float* W2 = (const float*)d_in[4];

    float* y      = (float*)d_out;              // [T, D]
    float* logits = y + (size_t)TT * DD;        // [T, E]

    zero_cnt_kernel<<<1, 32>>>();
    zero_y_kernel<<<(TT * DD / 4 + 255) / 256, 256>>>(y);
    probe_kernel<<<1, 32>>>();
    router_kernel<<<(TT * 32 + 255) / 256, 256>>>(x, Wg, logits);

    // MMA path (self-gated on g_mma_ok)
    {
        dim3 g(FF / 64, TT / 128, EE);
        up_mma_kernel<<<g, 256>>>(x, W1, W3);
    }
    {
        dim3 g(DD / 64, TT / 128, EE);
        down_mma_kernel<<<g, 256>>>(W2, y);
    }

    // SIMT fallback path (self-gated on !g_mma_ok)
    {
        dim3 g(FF / SBN, TT / SBM, EE);
        up_simt_kernel<<<g, 256>>>(x, W1, W3);
    }
    {
        dim3 g(DD / SBN, TT / SBM, EE);
        down_simt_kernel<<<g, 256>>>(W2);
    }
    combine_simt_kernel<<<(TT * DD / 4 + 255) / 256, 256>>>(y);
}

// round 8
// speedup vs baseline: 4.2196x; 1.2352x over previous
#include <cuda_runtime.h>
#include <cuda_fp16.h>
#include <math.h>
#include <stdint.h>

#define TT 4096   // tokens
#define DD 2048   // model dim
#define EE 8      // experts
#define FF 4096   // ffn dim
#define NA (2*TT) // assignments (top_k = 2)

// ---------------------------------------------------------------------------
// Helpers
// ---------------------------------------------------------------------------
__device__ __forceinline__ uint32_t smem_u32(const void* p) {
    uint32_t a;
    asm("{ .reg .u64 t; cvta.to.shared.u64 t, %1; cvt.u32.u64 %0, t; }"
        : "=r"(a) : "l"(p));
    return a;
}
__device__ __forceinline__ uint32_t lds32(uint32_t addr) {
    uint32_t v;
    asm volatile("ld.shared.b32 %0, [%1];" : "=r"(v) : "r"(addr));
    return v;
}
__device__ __forceinline__ void mma16816(float* c, const uint32_t* a, const uint32_t* b) {
    asm volatile("mma.sync.aligned.m16n8k16.row.col.f32.f16.f16.f32 "
        "{%0,%1,%2,%3}, {%4,%5,%6,%7}, {%8,%9}, {%0,%1,%2,%3};"
        : "+f"(c[0]), "+f"(c[1]), "+f"(c[2]), "+f"(c[3])
        : "r"(a[0]), "r"(a[1]), "r"(a[2]), "r"(a[3]), "r"(b[0]), "r"(b[1]));
}
__device__ __forceinline__ uint32_t pk2(float a, float b) {
    __half2 h = __floats2half2_rn(a, b);
    return *(uint32_t*)&h;
}

// ---------------------------------------------------------------------------
// Device-global scratch (~67 MB total; proven-safe envelope)
// ---------------------------------------------------------------------------
__device__ int    g_cnt[EE];
__device__ int    g_list[EE * TT];
__device__ float  g_wts[NA];
__device__ __half g_h16[(size_t)NA * FF];   // intermediate H (fp16)

// ---------------------------------------------------------------------------
__global__ void zero_cnt_kernel() {
    if (threadIdx.x < EE) g_cnt[threadIdx.x] = 0;
}

__global__ __launch_bounds__(256) void zero_y_kernel(float* __restrict__ y) {
    size_t i = ((size_t)blockIdx.x * 256 + threadIdx.x) * 4;
    if (i < (size_t)TT * DD) *(float4*)&y[i] = make_float4(0.f, 0.f, 0.f, 0.f);
}

// ---------------------------------------------------------------------------
// Router: one warp per token (verified R1/R6)
__global__ __launch_bounds__(256) void router_kernel(
    const float* __restrict__ x, const float* __restrict__ Wg,
    float* __restrict__ logits_out)
{
    int warp = (blockIdx.x * blockDim.x + threadIdx.x) >> 5;
    int lane = threadIdx.x & 31;
    if (warp >= TT) return;
    const float* xr = x + (size_t)warp * DD;
    float acc[EE];
#pragma unroll
    for (int e = 0; e < EE; e++) acc[e] = 0.f;
    for (int d = lane; d < DD; d += 32) {
        float xv = xr[d];
#pragma unroll
        for (int e = 0; e < EE; e++) acc[e] += xv * Wg[e * DD + d];
    }
#pragma unroll
    for (int e = 0; e < EE; e++)
#pragma unroll
        for (int off = 16; off; off >>= 1)
            acc[e] += __shfl_xor_sync(0xffffffffu, acc[e], off);
    if (lane == 0) {
#pragma unroll
        for (int e = 0; e < EE; e++) logits_out[warp * EE + e] = acc[e];
        int i0 = 0;
#pragma unroll
        for (int e = 1; e < EE; e++) if (acc[e] > acc[i0]) i0 = e;
        int i1 = -1;
#pragma unroll
        for (int e = 0; e < EE; e++) {
            if (e == i0) continue;
            if (i1 < 0 || acc[e] > acc[i1]) i1 = e;
        }
        float m  = fmaxf(acc[i0], acc[i1]);
        float e0 = expf(acc[i0] - m);
        float e1 = expf(acc[i1] - m);
        float inv = 1.f / (e0 + e1);
        g_wts[2 * warp + 0] = e0 * inv;
        g_wts[2 * warp + 1] = e1 * inv;
        int p0 = atomicAdd(&g_cnt[i0], 1);
        g_list[i0 * TT + p0] = 2 * warp + 0;
        int p1 = atomicAdd(&g_cnt[i1], 1);
        g_list[i1 * TT + p1] = 2 * warp + 1;
    }
}

// ---------------------------------------------------------------------------
// Fragment loaders for pad-40 rows (80B row stride), k-contiguous tiles.
__device__ __forceinline__ void ldfragA(uint32_t* a, uint32_t base, int R0, int ks, int lane) {
    int qr = lane >> 2;
    uint32_t kb = (uint32_t)(ks * 16 + (lane & 3) * 2) * 2u;
    uint32_t r0 = (uint32_t)(R0 + qr) * 80u;
    a[0] = lds32(base + r0 + kb);
    a[1] = lds32(base + r0 + 640u + kb);        // +8 rows
    a[2] = lds32(base + r0 + kb + 16u);         // +8 k
    a[3] = lds32(base + r0 + 640u + kb + 16u);
}
__device__ __forceinline__ void ldfragB(uint32_t* b, uint32_t base, int N0, int ks, int lane) {
    int qn = lane >> 2;
    uint32_t kb = (uint32_t)(ks * 16 + (lane & 3) * 2) * 2u;
    uint32_t n0 = (uint32_t)(N0 + qn) * 80u;
    b[0] = lds32(base + n0 + kb);
    b[1] = lds32(base + n0 + kb + 16u);
}

// ---------------------------------------------------------------------------
// Pass A (up): H = silu(Xg@W1) * (Xg@W3). CTA 128 rows x 64 F-cols, BK=32.
// Double-buffered SMEM, one sync per chunk. grid x=rt so concurrent CTAs
// share the (ct,e) weight tile via L2.
__global__ __launch_bounds__(256) void up_mma_kernel(
    const float* __restrict__ x, const float* __restrict__ W1,
    const float* __restrict__ W3)
{
    int rt = blockIdx.x, ct = blockIdx.y, e = blockIdx.z;
    int cnt = g_cnt[e];
    if (rt * 128 >= cnt) return;

    __shared__ int aid[128];
    __shared__ __align__(16) __half As[2][128][40];
    __shared__ __align__(16) __half B1s[2][64][40];
    __shared__ __align__(16) __half B3s[2][64][40];

    int tid = threadIdx.x, wid = tid >> 5, lane = tid & 31;
    if (tid < 128) {
        int r = rt * 128 + tid;
        aid[tid] = (r < cnt) ? g_list[e * TT + r] : -1;
    }
    __syncthreads();

    // A: 2 threads/row, 16 fp32 each along k. B: n=tid&63, k-group=(tid>>6)*8.
    int arow = tid >> 1, akq = (tid & 1) * 16;
    int aa = aid[arow];
    const float* xrow = x + (size_t)((aa >= 0) ? (aa >> 1) : 0) * DD;
    int bn = tid & 63, bkq = (tid >> 6) * 8;
    const float* w1p = W1 + (size_t)e * DD * FF + (size_t)ct * 64 + bn;
    const float* w3p = W3 + (size_t)e * DD * FF + (size_t)ct * 64 + bn;

    uint32_t aBase[2]  = { smem_u32(&As[0][0][0]),  smem_u32(&As[1][0][0]) };
    uint32_t b1Base[2] = { smem_u32(&B1s[0][0][0]), smem_u32(&B1s[1][0][0]) };
    uint32_t b3Base[2] = { smem_u32(&B3s[0][0][0]), smem_u32(&B3s[1][0][0]) };

    float acc1[2][4][4] = {}, acc3[2][4][4] = {};
    int wm = wid >> 1, wn = wid & 1;
    const int nc = DD / 32;            // 64 chunks

    float aR[16], b1R[8], b3R[8];

    // LDG chunk 0
    {
        const float* xp = xrow + akq;
        *(float4*)(aR + 0)  = *(const float4*)(xp + 0);
        *(float4*)(aR + 4)  = *(const float4*)(xp + 4);
        *(float4*)(aR + 8)  = *(const float4*)(xp + 8);
        *(float4*)(aR + 12) = *(const float4*)(xp + 12);
#pragma unroll
        for (int i = 0; i < 8; i++) {
            b1R[i] = w1p[(size_t)(bkq + i) * FF];
            b3R[i] = w3p[(size_t)(bkq + i) * FF];
        }
    }
    // STS chunk 0 -> stage 0
    {
        uint32_t ap[8];
#pragma unroll
        for (int j = 0; j < 8; j++) ap[j] = pk2(aR[2*j], aR[2*j+1]);
        *(uint4*)&As[0][arow][akq]     = make_uint4(ap[0], ap[1], ap[2], ap[3]);
        *(uint4*)&As[0][arow][akq + 8] = make_uint4(ap[4], ap[5], ap[6], ap[7]);
        uint32_t bp[4], cp[4];
#pragma unroll
        for (int j = 0; j < 4; j++) {
            bp[j] = pk2(b1R[2*j], b1R[2*j+1]);
            cp[j] = pk2(b3R[2*j], b3R[2*j+1]);
        }
        *(uint4*)&B1s[0][bn][bkq] = make_uint4(bp[0], bp[1], bp[2], bp[3]);
        *(uint4*)&B3s[0][bn][bkq] = make_uint4(cp[0], cp[1], cp[2], cp[3]);
    }

    for (int c = 0; c < nc; c++) {
        int s = c & 1;
        if (c + 1 < nc) {              // LDG chunk c+1 into regs
            int k0 = (c + 1) * 32;
            const float* xp = xrow + k0 + akq;
            *(float4*)(aR + 0)  = *(const float4*)(xp + 0);
            *(float4*)(aR + 4)  = *(const float4*)(xp + 4);
            *(float4*)(aR + 8)  = *(const float4*)(xp + 8);
            *(float4*)(aR + 12) = *(const float4*)(xp + 12);
#pragma unroll
            for (int i = 0; i < 8; i++) {
                b1R[i] = w1p[(size_t)(k0 + bkq + i) * FF];
                b3R[i] = w3p[(size_t)(k0 + bkq + i) * FF];
            }
        }
        __syncthreads();               // stage s fully written; s^1 compute done
#pragma unroll
        for (int ks = 0; ks < 2; ks++) {
            uint32_t a[2][4];
#pragma unroll
            for (int mt = 0; mt < 2; mt++)
                ldfragA(a[mt], aBase[s], wm * 32 + mt * 16, ks, lane);
#pragma unroll
            for (int nt = 0; nt < 4; nt++) {
                uint32_t b1[2], b3[2];
                ldfragB(b1, b1Base[s], wn * 32 + nt * 8, ks, lane);
                ldfragB(b3, b3Base[s], wn * 32 + nt * 8, ks, lane);
#pragma unroll
                for (int mt = 0; mt < 2; mt++) {
                    mma16816(acc1[mt][nt], a[mt], b1);
                    mma16816(acc3[mt][nt], a[mt], b3);
                }
            }
        }
        if (c + 1 < nc) {              // STS chunk c+1 -> stage s^1
            int d = s ^ 1;
            uint32_t ap[8];
#pragma unroll
            for (int j = 0; j < 8; j++) ap[j] = pk2(aR[2*j], aR[2*j+1]);
            *(uint4*)&As[d][arow][akq]     = make_uint4(ap[0], ap[1], ap[2], ap[3]);
            *(uint4*)&As[d][arow][akq + 8] = make_uint4(ap[4], ap[5], ap[6], ap[7]);
            uint32_t bp[4], cp[4];
#pragma unroll
            for (int j = 0; j < 4; j++) {
                bp[j] = pk2(b1R[2*j], b1R[2*j+1]);
                cp[j] = pk2(b3R[2*j], b3R[2*j+1]);
            }
            *(uint4*)&B1s[d][bn][bkq] = make_uint4(bp[0], bp[1], bp[2], bp[3]);
            *(uint4*)&B3s[d][bn][bkq] = make_uint4(cp[0], cp[1], cp[2], cp[3]);
        }
    }

    // epilogue: silu(acc1)*acc3 -> g_h16
#pragma unroll
    for (int mt = 0; mt < 2; mt++) {
#pragma unroll
        for (int h = 0; h < 2; h++) {
            int row = wm * 32 + mt * 16 + (lane >> 2) + h * 8;
            int a = aid[row];
            if (a < 0) continue;
            __half* hp = g_h16 + (size_t)a * FF + (size_t)ct * 64 + wn * 32 + 2 * (lane & 3);
#pragma unroll
            for (int nt = 0; nt < 4; nt++) {
                float v1a = acc1[mt][nt][h*2],   v1b = acc1[mt][nt][h*2+1];
                float v3a = acc3[mt][nt][h*2],   v3b = acc3[mt][nt][h*2+1];
                float ha = (v1a / (1.f + expf(-v1a))) * v3a;
                float hb = (v1b / (1.f + expf(-v1b))) * v3b;
                *(__half2*)(hp + nt * 8) = __floats2half2_rn(ha, hb);
            }
        }
    }
}

// ---------------------------------------------------------------------------
// Pass B (down): y += w * (H @ W2). CTA 128 rows x 64 D-cols, BK=32 over F.
// Double-buffered, one sync per chunk; grid x=rt for W2 L2 sharing.
__global__ __launch_bounds__(256) void down_mma_kernel(
    const float* __restrict__ W2, float* __restrict__ y)
{
    int rt = blockIdx.x, ct = blockIdx.y, e = blockIdx.z;
    int cnt = g_cnt[e];
    if (rt * 128 >= cnt) return;

    __shared__ int aid[128];
    __shared__ __align__(16) __half As[2][128][40];
    __shared__ __align__(16) __half Bs[2][64][40];

    int tid = threadIdx.x, wid = tid >> 5, lane = tid & 31;
    if (tid < 128) {
        int r = rt * 128 + tid;
        aid[tid] = (r < cnt) ? g_list[e * TT + r] : -1;
    }
    __syncthreads();

    int arow = tid >> 1, akq = (tid & 1) * 16;       // 16 halves each
    int aa = aid[arow];
    const __half* hrow = g_h16 + (size_t)((aa >= 0) ? aa : 0) * FF;
    int bn = tid & 63, bkq = (tid >> 6) * 8;
    const float* w2p = W2 + (size_t)e * FF * DD + (size_t)ct * 64 + bn;

    uint32_t aBase[2] = { smem_u32(&As[0][0][0]), smem_u32(&As[1][0][0]) };
    uint32_t bBase[2] = { smem_u32(&Bs[0][0][0]), smem_u32(&Bs[1][0][0]) };

    float acc[2][4][4] = {};
    int wm = wid >> 1, wn = wid & 1;
    const int nc = FF / 32;            // 128 chunks

    uint4 aU[2]; float bR[8];
    // LDG chunk 0
    {
        const __half* hp = hrow + akq;
        aU[0] = *(const uint4*)(hp);
        aU[1] = *(const uint4*)(hp + 8);
#pragma unroll
        for (int i = 0; i < 8; i++) bR[i] = w2p[(size_t)(bkq + i) * DD];
    }
    // STS chunk 0 -> stage 0
    {
        *(uint4*)&As[0][arow][akq]     = aU[0];
        *(uint4*)&As[0][arow][akq + 8] = aU[1];
        uint32_t bp[4];
#pragma unroll
        for (int j = 0; j < 4; j++) bp[j] = pk2(bR[2*j], bR[2*j+1]);
        *(uint4*)&Bs[0][bn][bkq] = make_uint4(bp[0], bp[1], bp[2], bp[3]);
    }

    for (int c = 0; c < nc; c++) {
        int s = c & 1;
        if (c + 1 < nc) {
            int k0 = (c + 1) * 32;
            const __half* hp = hrow + k0 + akq;
            aU[0] = *(const uint4*)(hp);
            aU[1] = *(const uint4*)(hp + 8);
#pragma unroll
            for (int i = 0; i < 8; i++) bR[i] = w2p[(size_t)(k0 + bkq + i) * DD];
        }
        __syncthreads();
#pragma unroll
        for (int ks = 0; ks < 2; ks++) {
            uint32_t a[2][4];
#pragma unroll
            for (int mt = 0; mt < 2; mt++)
                ldfragA(a[mt], aBase[s], wm * 32 + mt * 16, ks, lane);
#pragma unroll
            for (int nt = 0; nt < 4; nt++) {
                uint32_t b[2];
                ldfragB(b, bBase[s], wn * 32 + nt * 8, ks, lane);
#pragma unroll
                for (int mt = 0; mt < 2; mt++)
                    mma16816(acc[mt][nt], a[mt], b);
            }
        }
        if (c + 1 < nc) {
            int d = s ^ 1;
            *(uint4*)&As[d][arow][akq]     = aU[0];
            *(uint4*)&As[d][arow][akq + 8] = aU[1];
            uint32_t bp[4];
#pragma unroll
            for (int j = 0; j < 4; j++) bp[j] = pk2(bR[2*j], bR[2*j+1]);
            *(uint4*)&Bs[d][bn][bkq] = make_uint4(bp[0], bp[1], bp[2], bp[3]);
        }
    }

    // epilogue: exactly 2 commutative adds per y element -> deterministic
#pragma unroll
    for (int mt = 0; mt < 2; mt++) {
#pragma unroll
        for (int h = 0; h < 2; h++) {
            int row = wm * 32 + mt * 16 + (lane >> 2) + h * 8;
            int a = aid[row];
            if (a < 0) continue;
            float w = g_wts[a];
            float* yp = y + (size_t)(a >> 1) * DD + (size_t)ct * 64 + wn * 32 + 2 * (lane & 3);
#pragma unroll
            for (int nt = 0; nt < 4; nt++) {
                atomicAdd(yp + nt * 8,     w * acc[mt][nt][h*2]);
                atomicAdd(yp + nt * 8 + 1, w * acc[mt][nt][h*2+1]);
            }
        }
    }
}

// ---------------------------------------------------------------------------
extern "C" void kernel_launch(void* const* d_in, const int* in_sizes, int n_in,
                              void* d_out, int out_size)
{
    const float* x  = (const float*)d_in[0];
    const float* Wg = (const float*)d_in[1];
    const float* W1 = (const float*)d_in[2];
    const float* W3 = (const float*)d_in[3];
    const float* W2 = (const float*)d_in[4];

    float* y      = (float*)d_out;              // [T, D]
    float* logits = y + (size_t)TT * DD;        // [T, E]

    zero_cnt_kernel<<<1, 32>>>();
    zero_y_kernel<<<(TT * DD / 4 + 255) / 256, 256>>>(y);
    router_kernel<<<(TT * 32 + 255) / 256, 256>>>(x, Wg, logits);

    {   // x = rt (concurrent CTAs share weight tile), y = F-tile, z = expert
        dim3 g(TT / 128, FF / 64, EE);
        up_mma_kernel<<<g, 256>>>(x, W1, W3);
    }
    {   // x = rt, y = D-tile, z = expert
        dim3 g(TT / 128, DD / 64, EE);
        down_mma_kernel<<<g, 256>>>(W2, y);
    }
}

// round 11
// speedup vs baseline: 4.7615x; 1.1284x over previous
#include <cuda_runtime.h>
#include <cuda_fp16.h>
#include <math.h>
#include <stdint.h>

#define TT 4096   // tokens
#define DD 2048   // model dim
#define EE 8      // experts
#define FF 4096   // ffn dim
#define NA (2*TT) // assignments (top_k = 2)

// ---------------------------------------------------------------------------
// Helpers
// ---------------------------------------------------------------------------
__device__ __forceinline__ uint32_t smem_u32(const void* p) {
    uint32_t a;
    asm("{ .reg .u64 t; cvta.to.shared.u64 t, %1; cvt.u32.u64 %0, t; }"
        : "=r"(a) : "l"(p));
    return a;
}
__device__ __forceinline__ uint32_t lds32(uint32_t addr) {
    uint32_t v;
    asm volatile("ld.shared.b32 %0, [%1];" : "=r"(v) : "r"(addr));
    return v;
}
__device__ __forceinline__ void sts128(uint32_t addr, uint32_t x, uint32_t y,
                                       uint32_t z, uint32_t w) {
    asm volatile("st.shared.v4.b32 [%0], {%1,%2,%3,%4};"
                 :: "r"(addr), "r"(x), "r"(y), "r"(z), "r"(w));
}
__device__ __forceinline__ void mma16816(float* c, const uint32_t* a, const uint32_t* b) {
    asm volatile("mma.sync.aligned.m16n8k16.row.col.f32.f16.f16.f32 "
        "{%0,%1,%2,%3}, {%4,%5,%6,%7}, {%8,%9}, {%0,%1,%2,%3};"
        : "+f"(c[0]), "+f"(c[1]), "+f"(c[2]), "+f"(c[3])
        : "r"(a[0]), "r"(a[1]), "r"(a[2]), "r"(a[3]), "r"(b[0]), "r"(b[1]));
}
__device__ __forceinline__ uint32_t pk2(float a, float b) {
    __half2 h = __floats2half2_rn(a, b);
    return *(uint32_t*)&h;
}
// SW64 swizzle for 64B rows (32 halves).
__device__ __forceinline__ uint32_t swz(uint32_t off) {
    return off ^ ((off >> 3) & 0x30u);
}

// ---------------------------------------------------------------------------
// Device-global scratch (~217 MB total; inside proven-safe 268 MB envelope)
// ---------------------------------------------------------------------------
__device__ int    g_cnt[EE];
__device__ int    g_list[EE * TT];
__device__ float  g_wts[NA];
__device__ __half g_x16[(size_t)TT * DD];        // 16 MB
__device__ __half g_w2t[(size_t)EE * DD * FF];   // 134 MB: [E][D][F] fp16
__device__ __half g_h16[(size_t)NA * FF];        // 67 MB

// ---------------------------------------------------------------------------
__global__ void zero_cnt_kernel() {
    if (threadIdx.x < EE) g_cnt[threadIdx.x] = 0;
}

__global__ __launch_bounds__(256) void zero_y_kernel(float* __restrict__ y) {
    size_t i = ((size_t)blockIdx.x * 256 + threadIdx.x) * 4;
    if (i < (size_t)TT * DD) *(float4*)&y[i] = make_float4(0.f, 0.f, 0.f, 0.f);
}

__global__ __launch_bounds__(256) void cvtx_kernel(const float* __restrict__ x) {
    size_t i = ((size_t)blockIdx.x * 256 + threadIdx.x) * 4;
    if (i >= (size_t)TT * DD) return;
    float4 v = *(const float4*)&x[i];
    *(__half2*)&g_x16[i]     = __floats2half2_rn(v.x, v.y);
    *(__half2*)&g_x16[i + 2] = __floats2half2_rn(v.z, v.w);
}

// W2 [E][F][D] fp32 -> g_w2t [E][D][F] fp16 (transpose+convert)
__global__ __launch_bounds__(256) void tw2_kernel(const float* __restrict__ W2) {
    __shared__ float t[32][33];
    int e = blockIdx.z;
    int r0 = blockIdx.y * 32, c0 = blockIdx.x * 32;   // r over F, c over D
    int tx = threadIdx.x & 31, ty = threadIdx.x >> 5; // ty 0..7
    const float* ip = W2 + (size_t)e * FF * DD;
#pragma unroll
    for (int i = 0; i < 32; i += 8)
        t[ty + i][tx] = ip[(size_t)(r0 + ty + i) * DD + c0 + tx];
    __syncthreads();
    __half* op = g_w2t + (size_t)e * DD * FF;
#pragma unroll
    for (int i = 0; i < 32; i += 8)
        op[(size_t)(c0 + ty + i) * FF + r0 + tx] = __float2half_rn(t[tx][ty + i]);
}

// ---------------------------------------------------------------------------
// Router: one warp per token (verified)
__global__ __launch_bounds__(256) void router_kernel(
    const float* __restrict__ x, const float* __restrict__ Wg,
    float* __restrict__ logits_out)
{
    int warp = (blockIdx.x * blockDim.x + threadIdx.x) >> 5;
    int lane = threadIdx.x & 31;
    if (warp >= TT) return;
    const float* xr = x + (size_t)warp * DD;
    float acc[EE];
#pragma unroll
    for (int e = 0; e < EE; e++) acc[e] = 0.f;
    for (int d = lane; d < DD; d += 32) {
        float xv = xr[d];
#pragma unroll
        for (int e = 0; e < EE; e++) acc[e] += xv * Wg[e * DD + d];
    }
#pragma unroll
    for (int e = 0; e < EE; e++)
#pragma unroll
        for (int off = 16; off; off >>= 1)
            acc[e] += __shfl_xor_sync(0xffffffffu, acc[e], off);
    if (lane == 0) {
#pragma unroll
        for (int e = 0; e < EE; e++) logits_out[warp * EE + e] = acc[e];
        int i0 = 0;
#pragma unroll
        for (int e = 1; e < EE; e++) if (acc[e] > acc[i0]) i0 = e;
        int i1 = -1;
#pragma unroll
        for (int e = 0; e < EE; e++) {
            if (e == i0) continue;
            if (i1 < 0 || acc[e] > acc[i1]) i1 = e;
        }
        float m  = fmaxf(acc[i0], acc[i1]);
        float e0 = expf(acc[i0] - m);
        float e1 = expf(acc[i1] - m);
        float inv = 1.f / (e0 + e1);
        g_wts[2 * warp + 0] = e0 * inv;
        g_wts[2 * warp + 1] = e1 * inv;
        int p0 = atomicAdd(&g_cnt[i0], 1);
        g_list[i0 * TT + p0] = 2 * warp + 0;
        int p1 = atomicAdd(&g_cnt[i1], 1);
        g_list[i1 * TT + p1] = 2 * warp + 1;
    }
}

// ---------------------------------------------------------------------------
// Fragment loaders: 64B rows (32 halves), SW64 swizzle relative to tile base.
__device__ __forceinline__ void ldfragA(uint32_t* a, uint32_t base, int R0, int ks, int lane) {
    int qr = lane >> 2;
    uint32_t kb = (uint32_t)(ks * 16 + (lane & 3) * 2) * 2u;
    uint32_t r0 = (uint32_t)(R0 + qr) * 64u;
    a[0] = lds32(base + swz(r0 + kb));
    a[1] = lds32(base + swz(r0 + 512u + kb));       // +8 rows
    a[2] = lds32(base + swz(r0 + kb + 16u));        // +8 k
    a[3] = lds32(base + swz(r0 + 512u + kb + 16u));
}
__device__ __forceinline__ void ldfragB(uint32_t* b, uint32_t base, int N0, int ks, int lane) {
    int qn = lane >> 2;
    uint32_t kb = (uint32_t)(ks * 16 + (lane & 3) * 2) * 2u;
    uint32_t n0 = (uint32_t)(N0 + qn) * 64u;
    b[0] = lds32(base + swz(n0 + kb));
    b[1] = lds32(base + swz(n0 + kb + 16u));
}

// ---------------------------------------------------------------------------
// Pass A (up): H = silu(Xg@W1) * (Xg@W3). CTA 128 x 64, BK=32, double-buffered.
__global__ __launch_bounds__(256) void up_mma_kernel(
    const float* __restrict__ W1, const float* __restrict__ W3)
{
    int rt = blockIdx.x, ct = blockIdx.y, e = blockIdx.z;
    int cnt = g_cnt[e];
    if (rt * 128 >= cnt) return;

    __shared__ int aid[128];
    __shared__ __align__(1024) __half As[2][128][32];   // 16 KB
    __shared__ __align__(1024) __half B1s[2][64][32];   // 8 KB
    __shared__ __align__(1024) __half B3s[2][64][32];   // 8 KB

    int tid = threadIdx.x, wid = tid >> 5, lane = tid & 31;
    if (tid < 128) {
        int r = rt * 128 + tid;
        aid[tid] = (r < cnt) ? g_list[e * TT + r] : -1;
    }
    __syncthreads();

    // A: 2 threads/row, 16 halves (32 B) each. B: n=tid&63 rows, 8 k-values each.
    int arow = tid >> 1, aoff = (tid & 1) * 16;         // halves
    int aa = aid[arow];
    const __half* xrow = g_x16 + (size_t)((aa >= 0) ? (aa >> 1) : 0) * DD;
    int bn = tid & 63, bkq = (tid >> 6) * 8;
    const float* w1p = W1 + (size_t)e * DD * FF + (size_t)ct * 64 + bn;
    const float* w3p = W3 + (size_t)e * DD * FF + (size_t)ct * 64 + bn;

    uint32_t aBase[2]  = { smem_u32(&As[0][0][0]),  smem_u32(&As[1][0][0]) };
    uint32_t b1Base[2] = { smem_u32(&B1s[0][0][0]), smem_u32(&B1s[1][0][0]) };
    uint32_t b3Base[2] = { smem_u32(&B3s[0][0][0]), smem_u32(&B3s[1][0][0]) };

    uint32_t aRel = (uint32_t)arow * 64u + (uint32_t)(tid & 1) * 32u;  // bytes
    uint32_t bRel = (uint32_t)bn * 64u + (uint32_t)bkq * 2u;           // bytes

    float acc1[2][4][4] = {}, acc3[2][4][4] = {};
    int wm = wid >> 1, wn = wid & 1;
    const int nc = DD / 32;            // 64 chunks

    uint4 aU0, aU1; float b1R[8], b3R[8];

    // LDG chunk 0
    {
        const __half* xp = xrow + aoff;
        aU0 = *(const uint4*)(xp);
        aU1 = *(const uint4*)(xp + 8);
#pragma unroll
        for (int i = 0; i < 8; i++) {
            b1R[i] = w1p[(size_t)(bkq + i) * FF];
            b3R[i] = w3p[(size_t)(bkq + i) * FF];
        }
    }
    // STS chunk 0 -> stage 0  (two 16B stores: bytes +0 and +16 of this thread's 32B)
    {
        sts128(aBase[0] + swz(aRel),       aU0.x, aU0.y, aU0.z, aU0.w);
        sts128(aBase[0] + swz(aRel + 16u), aU1.x, aU1.y, aU1.z, aU1.w);
        uint32_t bp[4], cp[4];
#pragma unroll
        for (int j = 0; j < 4; j++) {
            bp[j] = pk2(b1R[2*j], b1R[2*j+1]);
            cp[j] = pk2(b3R[2*j], b3R[2*j+1]);
        }
        sts128(b1Base[0] + swz(bRel), bp[0], bp[1], bp[2], bp[3]);
        sts128(b3Base[0] + swz(bRel), cp[0], cp[1], cp[2], cp[3]);
    }

    for (int c = 0; c < nc; c++) {
        int s = c & 1;
        if (c + 1 < nc) {              // LDG chunk c+1
            int k0 = (c + 1) * 32;
            const __half* xp = xrow + k0 + aoff;
            aU0 = *(const uint4*)(xp);
            aU1 = *(const uint4*)(xp + 8);
#pragma unroll
            for (int i = 0; i < 8; i++) {
                b1R[i] = w1p[(size_t)(k0 + bkq + i) * FF];
                b3R[i] = w3p[(size_t)(k0 + bkq + i) * FF];
            }
        }
        __syncthreads();               // stage s ready; s^1 compute done
#pragma unroll
        for (int ks = 0; ks < 2; ks++) {
            uint32_t a[2][4];
#pragma unroll
            for (int mt = 0; mt < 2; mt++)
                ldfragA(a[mt], aBase[s], wm * 32 + mt * 16, ks, lane);
#pragma unroll
            for (int nt = 0; nt < 4; nt++) {
                uint32_t b1[2], b3[2];
                ldfragB(b1, b1Base[s], wn * 32 + nt * 8, ks, lane);
                ldfragB(b3, b3Base[s], wn * 32 + nt * 8, ks, lane);
#pragma unroll
                for (int mt = 0; mt < 2; mt++) {
                    mma16816(acc1[mt][nt], a[mt], b1);
                    mma16816(acc3[mt][nt], a[mt], b3);
                }
            }
        }
        if (c + 1 < nc) {              // STS chunk c+1 -> stage s^1
            int d = s ^ 1;
            sts128(aBase[d] + swz(aRel),       aU0.x, aU0.y, aU0.z, aU0.w);
            sts128(aBase[d] + swz(aRel + 16u), aU1.x, aU1.y, aU1.z, aU1.w);
            uint32_t bp[4], cp[4];
#pragma unroll
            for (int j = 0; j < 4; j++) {
                bp[j] = pk2(b1R[2*j], b1R[2*j+1]);
                cp[j] = pk2(b3R[2*j], b3R[2*j+1]);
            }
            sts128(b1Base[d] + swz(bRel), bp[0], bp[1], bp[2], bp[3]);
            sts128(b3Base[d] + swz(bRel), cp[0], cp[1], cp[2], cp[3]);
        }
    }

    // epilogue: silu(acc1)*acc3 -> g_h16
#pragma unroll
    for (int mt = 0; mt < 2; mt++) {
#pragma unroll
        for (int h = 0; h < 2; h++) {
            int row = wm * 32 + mt * 16 + (lane >> 2) + h * 8;
            int a = aid[row];
            if (a < 0) continue;
            __half* hp = g_h16 + (size_t)a * FF + (size_t)ct * 64 + wn * 32 + 2 * (lane & 3);
#pragma unroll
            for (int nt = 0; nt < 4; nt++) {
                float v1a = acc1[mt][nt][h*2],   v1b = acc1[mt][nt][h*2+1];
                float v3a = acc3[mt][nt][h*2],   v3b = acc3[mt][nt][h*2+1];
                float ha = (v1a / (1.f + expf(-v1a))) * v3a;
                float hb = (v1b / (1.f + expf(-v1b))) * v3b;
                *(__half2*)(hp + nt * 8) = __floats2half2_rn(ha, hb);
            }
        }
    }
}

// ---------------------------------------------------------------------------
// Pass B (down): y += w * (H @ W2t). CTA 128 x 64, BK=32 over F. All-fp16 loads.
__global__ __launch_bounds__(256) void down_mma_kernel(float* __restrict__ y)
{
    int rt = blockIdx.x, ct = blockIdx.y, e = blockIdx.z;
    int cnt = g_cnt[e];
    if (rt * 128 >= cnt) return;

    __shared__ int aid[128];
    __shared__ __align__(1024) __half As[2][128][32];
    __shared__ __align__(1024) __half Bs[2][64][32];

    int tid = threadIdx.x, wid = tid >> 5, lane = tid & 31;
    if (tid < 128) {
        int r = rt * 128 + tid;
        aid[tid] = (r < cnt) ? g_list[e * TT + r] : -1;
    }
    __syncthreads();

    int arow = tid >> 1, aoff = (tid & 1) * 16;
    int aa = aid[arow];
    const __half* hrow = g_h16 + (size_t)((aa >= 0) ? aa : 0) * FF;
    int brow = tid >> 2, bc = tid & 3;                 // 4 threads/row, 8 halves each
    const __half* bsrc = g_w2t + ((size_t)e * DD + (size_t)ct * 64 + brow) * FF + bc * 8;

    uint32_t aBase[2] = { smem_u32(&As[0][0][0]), smem_u32(&As[1][0][0]) };
    uint32_t bBase[2] = { smem_u32(&Bs[0][0][0]), smem_u32(&Bs[1][0][0]) };

    uint32_t aRel = (uint32_t)arow * 64u + (uint32_t)(tid & 1) * 32u;
    uint32_t bRel = (uint32_t)brow * 64u + (uint32_t)bc * 16u;

    float acc[2][4][4] = {};
    int wm = wid >> 1, wn = wid & 1;
    const int nc = FF / 32;            // 128 chunks

    uint4 aU0, aU1, bU;
    {
        const __half* hp = hrow + aoff;
        aU0 = *(const uint4*)(hp);
        aU1 = *(const uint4*)(hp + 8);
        bU  = *(const uint4*)(bsrc);
    }
    {
        sts128(aBase[0] + swz(aRel),       aU0.x, aU0.y, aU0.z, aU0.w);
        sts128(aBase[0] + swz(aRel + 16u), aU1.x, aU1.y, aU1.z, aU1.w);
        sts128(bBase[0] + swz(bRel),       bU.x, bU.y, bU.z, bU.w);
    }

    for (int c = 0; c < nc; c++) {
        int s = c & 1;
        if (c + 1 < nc) {
            int k0 = (c + 1) * 32;
            const __half* hp = hrow + k0 + aoff;
            aU0 = *(const uint4*)(hp);
            aU1 = *(const uint4*)(hp + 8);
            bU  = *(const uint4*)(bsrc + k0);
        }
        __syncthreads();
#pragma unroll
        for (int ks = 0; ks < 2; ks++) {
            uint32_t a[2][4];
#pragma unroll
            for (int mt = 0; mt < 2; mt++)
                ldfragA(a[mt], aBase[s], wm * 32 + mt * 16, ks, lane);
#pragma unroll
            for (int nt = 0; nt < 4; nt++) {
                uint32_t b[2];
                ldfragB(b, bBase[s], wn * 32 + nt * 8, ks, lane);
#pragma unroll
                for (int mt = 0; mt < 2; mt++)
                    mma16816(acc[mt][nt], a[mt], b);
            }
        }
        if (c + 1 < nc) {
            int d = s ^ 1;
            sts128(aBase[d] + swz(aRel),       aU0.x, aU0.y, aU0.z, aU0.w);
            sts128(aBase[d] + swz(aRel + 16u), aU1.x, aU1.y, aU1.z, aU1.w);
            sts128(bBase[d] + swz(bRel),       bU.x, bU.y, bU.z, bU.w);
        }
    }

    // epilogue: exactly 2 commutative adds per y element -> deterministic
#pragma unroll
    for (int mt = 0; mt < 2; mt++) {
#pragma unroll
        for (int h = 0; h < 2; h++) {
            int row = wm * 32 + mt * 16 + (lane >> 2) + h * 8;
            int a = aid[row];
            if (a < 0) continue;
            float w = g_wts[a];
            float* yp = y + (size_t)(a >> 1) * DD + (size_t)ct * 64 + wn * 32 + 2 * (lane & 3);
#pragma unroll
            for (int nt = 0; nt < 4; nt++) {
                atomicAdd(yp + nt * 8,     w * acc[mt][nt][h*2]);
                atomicAdd(yp + nt * 8 + 1, w * acc[mt][nt][h*2+1]);
            }
        }
    }
}

// ---------------------------------------------------------------------------
extern "C" void kernel_launch(void* const* d_in, const int* in_sizes, int n_in,
                              void* d_out, int out_size)
{
    const float* x  = (const float*)d_in[0];
    const float* Wg = (const float*)d_in[1];
    const float* W1 = (const float*)d_in[2];
    const float* W3 = (const float*)d_in[3];
    const float* W2 = (const float*)d_in[4];

    float* y      = (float*)d_out;              // [T, D]
    float* logits = y + (size_t)TT * DD;        // [T, E]

    zero_cnt_kernel<<<1, 32>>>();
    zero_y_kernel<<<(TT * DD / 4 + 255) / 256, 256>>>(y);
    cvtx_kernel<<<(TT * DD / 4 + 255) / 256, 256>>>(x);
    {   // W2 [E][F][D] -> [E][D][F] fp16
        dim3 g(DD / 32, FF / 32, EE);
        tw2_kernel<<<g, 256>>>(W2);
    }
    router_kernel<<<(TT * 32 + 255) / 256, 256>>>(x, Wg, logits);

    {   // x = rt (concurrent CTAs share weight tile via L2)
        dim3 g(TT / 128, FF / 64, EE);
        up_mma_kernel<<<g, 256>>>(W1, W3);
    }
    {
        dim3 g(TT / 128, DD / 64, EE);
        down_mma_kernel<<<g, 256>>>(y);
    }
}